// round 1
// baseline (speedup 1.0000x reference)
#include <cuda_runtime.h>
#include <math.h>

#define NSTEPS 130
#define NLUT   27          // 9 triangles x 3 LUTs
#define NVEC   (NSTEPS * NLUT)   // 3510 float4s of noise

// Wiring tables: flat state is prev[9][3] (indices 0..26) ++ x (27=a, 28=b).
__device__ __constant__ int c_IDX0[9] = {3, 0, 6, 12, 9, 15, 18, 6, 15};
__device__ __constant__ int c_IDX1[9] = {1, 7, 4, 19, 16, 13, 10, 22, 25};
__device__ __constant__ int c_IDX2[9] = {17, 5, 11, 8, 28, 2, 27, 23, 26};

__global__ void one_layer_net_kernel(const float* __restrict__ x,
                                     const float* __restrict__ weights,
                                     const float4* __restrict__ noise4,
                                     float* __restrict__ out) {
    extern __shared__ float4 s_noise[];   // [130*27] float4 = 56160 B

    const int tid = threadIdx.x;

    // Cooperative preload of all noise into SMEM (all 256 threads).
    for (int i = tid; i < NVEC; i += blockDim.x)
        s_noise[i] = noise4[i];
    __syncthreads();

    if (tid >= 32) return;   // only warp 0 runs the serial scan

    const int  lane   = tid;
    const bool active = (lane < NLUT);
    const int  t = lane / 3;
    const int  j = lane % 3;

    int l0 = 0, l1 = 0, l2 = 0;
    float4 w = make_float4(0.f, 0.f, 0.f, 0.f);
    float4 c = make_float4(0.f, 0.f, 0.f, 0.f);
    float  state;

    if (active) {
        l0 = c_IDX0[t];
        l1 = c_IDX1[t];
        l2 = c_IDX2[t];
        w = reinterpret_cast<const float4*>(weights)[lane];
        // step-invariant noise gain: |1 - |w|| * 0.125
        c.x = fabsf(1.0f - fabsf(w.x)) * 0.125f;
        c.y = fabsf(1.0f - fabsf(w.y)) * 0.125f;
        c.z = fabsf(1.0f - fabsf(w.z)) * 0.125f;
        c.w = fabsf(1.0f - fabsf(w.w)) * 0.125f;
        state = -1.0f;
    } else {
        // lanes 27/28 carry the constant inputs a=x[0], b=x[1]; 29..31 are padding
        state = (lane == 27) ? x[0] : ((lane == 28) ? x[1] : 0.0f);
    }

    const int ll = active ? lane : 0;    // safe SMEM index for padding lanes

    // Software pipeline: hold this step's noise, prefetch next step's.
    float4 n = s_noise[ll];

#pragma unroll 2
    for (int s = 0; s < NSTEPS; ++s) {
        // Prefetch next step's noise early (LDS lat ~29 overlaps shfl lat ~26).
        const int nidx = (s + 1 < NSTEPS) ? (s + 1) * NLUT + ll : ll;
        const float4 nn = s_noise[nidx];

        // Gather the three wired inputs from the warp-held flat state.
        const float x0 = __shfl_sync(0xFFFFFFFFu, state, l0);
        const float x1 = __shfl_sync(0xFFFFFFFFu, state, l1);
        const float x2 = __shfl_sync(0xFFFFFFFFu, state, l2);

        // Perturbed weights: w + c*n (4 FMAs).
        const float w0 = fmaf(c.x, n.x, w.x);
        const float w1 = fmaf(c.y, n.y, w.y);
        const float w2 = fmaf(c.z, n.z, w.z);
        const float w3 = fmaf(c.w, n.w, w.w);

        // Mux selects per LUT position: A = {x1,x0,x0}[j], B = {x2,x2,x1}[j].
        const float A = (j == 0) ? x1 : x0;
        const float B = (j == 2) ? x1 : x2;

        // mux(s,a,b) = 0.5*(s*(b-a) + (a+b))
        const float m0 = 0.5f * fmaf(A, w1 - w0, w0 + w1);
        const float m1 = 0.5f * fmaf(A, w3 - w2, w2 + w3);
        const float nv = 0.5f * fmaf(B, m1 - m0, m0 + m1);

        state = active ? nv : state;   // lanes 27/28 keep constant x values
        n = nn;
    }

    // Outputs: final[0,1] -> flat 1, final[1,2] -> flat 5, final[7,2] -> flat 23.
    if (lane == 1)  out[0] = state;
    if (lane == 5)  out[1] = state;
    if (lane == 23) out[2] = state;
}

extern "C" void kernel_launch(void* const* d_in, const int* in_sizes, int n_in,
                              void* d_out, int out_size) {
    (void)in_sizes; (void)n_in; (void)out_size;
    const float*  x  = (const float*)d_in[0];      // [2]
    const float*  w  = (const float*)d_in[1];      // [9,3,4]
    const float4* nz = (const float4*)d_in[2];     // [130,9,3,4] as float4
    float* out = (float*)d_out;                    // [3]

    const size_t smem = (size_t)NVEC * sizeof(float4);   // 56160 B > 48KB static limit
    cudaFuncSetAttribute(one_layer_net_kernel,
                         cudaFuncAttributeMaxDynamicSharedMemorySize, (int)smem);
    one_layer_net_kernel<<<1, 256, smem>>>(x, w, nz, out);
}